// round 14
// baseline (speedup 1.0000x reference)
#include <cuda_runtime.h>
#include <cuda_bf16.h>
#include <cstdint>
#include <cstdio>
#include <math_constants.h>

// Problem shape (fixed by the dataset)
#define NN   30000
#define EE   480000
#define INX  3000
#define INR  2048
#define NH   256
#define OUTD 64
#define D2   (2*NH)   // 512

// ---------------- scratch (device globals; no allocs allowed) ----------------
__device__ float    g_H1x [(size_t)NN*NH];
__device__ float    g_H1r [(size_t)NN*NH];
__device__ float    g_Hgx [(size_t)NN*NH];
__device__ float    g_Hgr [(size_t)NN*NH];
__device__ float    g_t   [(size_t)NN*D2];
__device__ float    g_hdec[(size_t)NN*D2];
__device__ float    g_h3  [(size_t)NN*D2];
__device__ float    g_es  [NN];
__device__ float    g_ed  [NN];
__device__ int      g_deg [NN];
__device__ int      g_rs  [NN + 1];
__device__ int      g_cur [NN];
__device__ int      g_csrc[EE];
// pre-converted (tf32 bit pattern) weights, [N][K] row-major per GEMM use
__device__ float    g_W1xc[(size_t)INX*NH];
__device__ float    g_W1rc[(size_t)INR*NH];
__device__ float    g_W2c [(size_t)D2*OUTD];
__device__ float    g_W1xt[(size_t)NH*INX];
__device__ float    g_W1rt[(size_t)NH*INR];
__device__ float    g_W2t [(size_t)OUTD*D2];

// ---------------- unified TF32 GEMM: C[M,N] = A[M,K] @ Bt^T ----------------
// A: fp32 (or pre-rounded tf32 bits if !CVT_A) [M][K].  Bt: tf32-bit [N][K].
#define GBM 128
#define GBN 128
#define GBK 16
#define STAGES 5
#define AS_STRIDE 20
#define BS_STRIDE 20

#define A_STG (GBM * AS_STRIDE)
#define B_STG (GBN * BS_STRIDE)

__device__ __forceinline__ unsigned f2tf32(float f) {
    unsigned r;
    asm("cvt.rna.tf32.f32 %0, %1;" : "=r"(r) : "f"(f));
    return r;
}
__device__ __forceinline__ float f2tf32f(float f) {
    return __uint_as_float(f2tf32(f));
}

__device__ __forceinline__ void cp_async16(uint32_t saddr, const void* gptr, int src_size) {
    asm volatile("cp.async.cg.shared.global [%0], [%1], 16, %2;\n"
                 :: "r"(saddr), "l"(gptr), "r"(src_size));
}
__device__ __forceinline__ void cp_commit() {
    asm volatile("cp.async.commit_group;\n");
}
template<int NWAIT>
__device__ __forceinline__ void cp_wait() {
    asm volatile("cp.async.wait_group %0;\n" :: "n"(NWAIT));
}

__device__ __forceinline__ void ldsm_x4(unsigned r[4], uint32_t saddr) {
    asm volatile("ldmatrix.sync.aligned.m8n8.x4.shared.b16 {%0,%1,%2,%3}, [%4];"
                 : "=r"(r[0]), "=r"(r[1]), "=r"(r[2]), "=r"(r[3]) : "r"(saddr));
}

__device__ __forceinline__ void mma_tf32(float c[4],
                                         unsigned a0, unsigned a1, unsigned a2, unsigned a3,
                                         unsigned b0, unsigned b1) {
    asm volatile(
        "mma.sync.aligned.m16n8k8.row.col.f32.tf32.tf32.f32 "
        "{%0,%1,%2,%3}, {%4,%5,%6,%7}, {%8,%9}, {%0,%1,%2,%3};"
        : "+f"(c[0]), "+f"(c[1]), "+f"(c[2]), "+f"(c[3])
        : "r"(a0), "r"(a1), "r"(a2), "r"(a3), "r"(b0), "r"(b1));
}

template<bool CVT_A>
__global__ __launch_bounds__(256)
void tf32_gemm(const float* __restrict__ A, const float* __restrict__ Bt,
               float* __restrict__ C, int M, int N, int K,
               int lda, int ldb, int ldc) {
    extern __shared__ float smem[];
    float* As = smem;
    float* Bs = smem + STAGES * A_STG;

    const int tid  = threadIdx.x;
    const int lane = tid & 31;
    const int wid  = tid >> 5;
    const int wm   = wid & 3;
    const int wn   = wid >> 2;
    const int bm   = blockIdx.y * GBM;
    const int bn   = blockIdx.x * GBN;
    const int grp  = lane >> 2;
    const int tig  = lane & 3;

    const bool full = (bm + GBM <= M) && (bn + GBN <= N);

    float acc[2][8][4];
    #pragma unroll
    for (int i = 0; i < 2; i++)
        #pragma unroll
        for (int j = 0; j < 8; j++)
            #pragma unroll
            for (int q = 0; q < 4; q++) acc[i][j][q] = 0.f;

    const int ar  = tid >> 1;
    const int ah  = (tid & 1) * 2;

    const float* Agbase;
    {
        int m = bm + ar;
        Agbase = A + (size_t)(full ? m : min(m, M - 1)) * lda;
    }
    const bool a_row_ok = full || (bm + ar < M);

    const float* Bgbase;
    {
        int n = bn + ar;
        Bgbase = Bt + (size_t)(full ? n : min(n, N - 1)) * ldb;
    }
    const bool b_row_ok = full || (bn + ar < N);

    auto issue_tile = [&](int t, int stage) {
        const int k0 = t * GBK;
        #pragma unroll
        for (int h = 0; h < 2; h++) {
            int q = ah + h;
            int k = k0 + q * 4;
            bool ok = a_row_ok && (k + 4 <= K);
            uint32_t sa = (uint32_t)__cvta_generic_to_shared(
                &As[stage * A_STG + ar * AS_STRIDE + q * 4]);
            cp_async16(sa, Agbase + (ok ? k : 0), ok ? 16 : 0);
        }
        #pragma unroll
        for (int h = 0; h < 2; h++) {
            int q = ah + h;
            int k = k0 + q * 4;
            bool ok = b_row_ok && (k + 4 <= K);
            uint32_t sa = (uint32_t)__cvta_generic_to_shared(
                &Bs[stage * B_STG + ar * BS_STRIDE + q * 4]);
            cp_async16(sa, Bgbase + (ok ? k : 0), ok ? 16 : 0);
        }
    };

    const uint32_t as_base = (uint32_t)__cvta_generic_to_shared(As);
    const uint32_t bs_base = (uint32_t)__cvta_generic_to_shared(Bs);
    const uint32_t a_frag = ((wm * 32 + (lane & 15)) * AS_STRIDE + ((lane >> 4) << 2)) * 4;
    const uint32_t b_frag = ((wn * 64 + (lane & 7) + ((lane >> 4) << 3)) * BS_STRIDE
                             + ((lane & 8) >> 1)) * 4;

    const int nk = (K + GBK - 1) / GBK;

    #pragma unroll
    for (int s = 0; s < STAGES - 1; s++) {
        if (s < nk) issue_tile(s, s);
        cp_commit();
    }

    for (int t = 0; t < nk; t++) {
        cp_wait<STAGES - 2>();
        __syncthreads();
        const int buf = t % STAGES;
        const uint32_t abuf = as_base + buf * (A_STG * 4) + a_frag;
        const uint32_t bbuf = bs_base + buf * (B_STG * 4) + b_frag;

        #pragma unroll
        for (int ks = 0; ks < 2; ks++) {
            const uint32_t kofb = ks * 32;
            unsigned af[2][4];
            #pragma unroll
            for (int i = 0; i < 2; i++) {
                ldsm_x4(af[i], abuf + i * (16 * AS_STRIDE * 4) + kofb);
                if (CVT_A) {
                    af[i][0] = f2tf32(__uint_as_float(af[i][0]));
                    af[i][1] = f2tf32(__uint_as_float(af[i][1]));
                    af[i][2] = f2tf32(__uint_as_float(af[i][2]));
                    af[i][3] = f2tf32(__uint_as_float(af[i][3]));
                }
            }
            #pragma unroll
            for (int jp = 0; jp < 4; jp++) {
                unsigned bq[4];
                ldsm_x4(bq, bbuf + jp * (16 * BS_STRIDE * 4) + kofb);
                #pragma unroll
                for (int i = 0; i < 2; i++) {
                    mma_tf32(acc[i][2 * jp    ], af[i][0], af[i][1], af[i][2], af[i][3], bq[0], bq[1]);
                    mma_tf32(acc[i][2 * jp + 1], af[i][0], af[i][1], af[i][2], af[i][3], bq[2], bq[3]);
                }
            }
        }

        int nt = t + STAGES - 1;
        if (nt < nk) issue_tile(nt, nt % STAGES);
        cp_commit();
    }

    #pragma unroll
    for (int i = 0; i < 2; i++) {
        int r0 = bm + wm * 32 + i * 16 + grp;
        int r1 = r0 + 8;
        #pragma unroll
        for (int j = 0; j < 8; j++) {
            int c = bn + wn * 64 + j * 8 + 2 * tig;
            if (full || r0 < M) {
                if (full || c + 1 < N) *(float2*)&C[(size_t)r0 * ldc + c] = make_float2(acc[i][j][0], acc[i][j][1]);
                else if (c < N) C[(size_t)r0 * ldc + c] = acc[i][j][0];
            }
            if (full || r1 < M) {
                if (full || c + 1 < N) *(float2*)&C[(size_t)r1 * ldc + c] = make_float2(acc[i][j][2], acc[i][j][3]);
                else if (c < N) C[(size_t)r1 * ldc + c] = acc[i][j][2];
            }
        }
    }
}

static int smem_bytes() { return (STAGES * (A_STG + B_STG)) * 4; }

template<bool CVT_A>
static void sgemm(const float* A, const float* Bt, float* C,
                  int M, int N, int K, int lda) {
    dim3 grid((N + GBN - 1) / GBN, (M + GBM - 1) / GBM);
    tf32_gemm<CVT_A><<<grid, 256, smem_bytes()>>>(A, Bt, C, M, N, K, lda, K, N);
}

// weight pre-conversion: fp32 -> tf32 bit pattern
__global__ void cvt_tf32_kernel(const float* __restrict__ in, float* __restrict__ out, int n) {
    int i = blockIdx.x * blockDim.x + threadIdx.x;
    if (i < n) out[i] = f2tf32f(in[i]);
}

// transpose + convert: in [R][Cc] -> out [Cc][R] (tf32 bits)
__global__ void transpose_cvt_kernel(const float* __restrict__ in, float* __restrict__ out,
                                     int R, int Cc) {
    __shared__ float tile[32][33];
    int c = blockIdx.x * 32 + threadIdx.x;
    int r0 = blockIdx.y * 32;
    #pragma unroll
    for (int dy = 0; dy < 32; dy += 8) {
        int r = r0 + threadIdx.y + dy;
        if (r < R && c < Cc) tile[threadIdx.y + dy][threadIdx.x] = in[(size_t)r * Cc + c];
    }
    __syncthreads();
    int oc = r0 + threadIdx.x;
    #pragma unroll
    for (int dy = 0; dy < 32; dy += 8) {
        int orow = blockIdx.x * 32 + threadIdx.y + dy;
        if (orow < Cc && oc < R)
            out[(size_t)orow * R + oc] = f2tf32f(tile[threadIdx.x][threadIdx.y + dy]);
    }
}

// ---------------- CSR build ----------------

__global__ void deg_kernel(const int* __restrict__ dst, int* __restrict__ deg, int E) {
    int e = blockIdx.x * blockDim.x + threadIdx.x;
    if (e < E) atomicAdd(&deg[dst[e]], 1);
}

__global__ void scan_kernel(const int* __restrict__ deg, int* __restrict__ rs, int N) {
    __shared__ int sm[1024];
    __shared__ int carry_s;
    if (threadIdx.x == 0) carry_s = 0;
    __syncthreads();
    for (int base = 0; base < N; base += 1024) {
        int i = base + threadIdx.x;
        int v = (i < N) ? deg[i] : 0;
        sm[threadIdx.x] = v;
        __syncthreads();
        #pragma unroll
        for (int off = 1; off < 1024; off <<= 1) {
            int t = (threadIdx.x >= off) ? sm[threadIdx.x - off] : 0;
            __syncthreads();
            sm[threadIdx.x] += t;
            __syncthreads();
        }
        int incl = sm[threadIdx.x];
        int carry = carry_s;
        if (i < N) rs[i] = carry + incl - v;
        int total = sm[1023];
        __syncthreads();
        if (threadIdx.x == 0) carry_s = carry + total;
        __syncthreads();
    }
    if (threadIdx.x == 0) rs[N] = carry_s;
}

__global__ void scatter_kernel(const int* __restrict__ src, const int* __restrict__ dst,
                               int* __restrict__ cur, int* __restrict__ csrc, int E) {
    int e = blockIdx.x * blockDim.x + threadIdx.x;
    if (e >= E) return;
    int slot = atomicAdd(&cur[dst[e]], 1);
    csrc[slot] = src[e];
}

// ---------------- fused GAT: softmax + aggregate + ELU (+ tf32 rounding) ----------------
// ROUND_OUT: output is consumed only as a tf32-GEMM A operand -> store pre-rounded
// (bit-identical to the GEMM's own internal rounding; zero extra error).
template<int DCH, bool ROUND_OUT>
__global__ void gat_fused_kernel(const float* __restrict__ H,
                                 const float* __restrict__ es,
                                 const float* __restrict__ ed,
                                 const int* __restrict__ rs,
                                 const int* __restrict__ csrc,
                                 float* __restrict__ out, int ldo, int N) {
    int node = (blockIdx.x * blockDim.x + threadIdx.x) >> 5;
    int lane = threadIdx.x & 31;
    if (node >= N) return;
    int s0 = rs[node], s1 = rs[node + 1];

    float4 acc[DCH];
    #pragma unroll
    for (int c = 0; c < DCH; c++) acc[c] = make_float4(0.f, 0.f, 0.f, 0.f);

    if (s0 < s1) {
        const float edv = ed[node];
        float mx = -CUDART_INF_F;
        for (int i = s0 + lane; i < s1; i += 32) {
            float v = es[csrc[i]] + edv;
            v = v > 0.f ? v : 0.2f * v;
            mx = fmaxf(mx, v);
        }
        #pragma unroll
        for (int o = 16; o; o >>= 1) mx = fmaxf(mx, __shfl_xor_sync(0xffffffffu, mx, o));

        float ssum = 0.f;
        for (int i = s0 + lane; i < s1; i += 32) {
            float v = es[csrc[i]] + edv;
            v = v > 0.f ? v : 0.2f * v;
            ssum += expf(v - mx);
        }
        #pragma unroll
        for (int o = 16; o; o >>= 1) ssum += __shfl_xor_sync(0xffffffffu, ssum, o);
        float inv = 1.f / (ssum + 1e-16f);

        for (int i = s0; i < s1; i++) {
            int s = csrc[i];
            float v = es[s] + edv;
            v = v > 0.f ? v : 0.2f * v;
            float alpha = expf(v - mx) * inv;
            const float4* hrow = (const float4*)(H + (size_t)s * (DCH * 128));
            #pragma unroll
            for (int c = 0; c < DCH; c++) {
                float4 hv = hrow[c * 32 + lane];
                acc[c].x = fmaf(alpha, hv.x, acc[c].x);
                acc[c].y = fmaf(alpha, hv.y, acc[c].y);
                acc[c].z = fmaf(alpha, hv.z, acc[c].z);
                acc[c].w = fmaf(alpha, hv.w, acc[c].w);
            }
        }
    }

    float4* orow = (float4*)(out + (size_t)node * ldo);
    #pragma unroll
    for (int c = 0; c < DCH; c++) {
        float4 v = acc[c];
        v.x = v.x > 0.f ? v.x : expm1f(v.x);
        v.y = v.y > 0.f ? v.y : expm1f(v.y);
        v.z = v.z > 0.f ? v.z : expm1f(v.z);
        v.w = v.w > 0.f ? v.w : expm1f(v.w);
        if (ROUND_OUT) {
            v.x = f2tf32f(v.x); v.y = f2tf32f(v.y);
            v.z = f2tf32f(v.z); v.w = f2tf32f(v.w);
        }
        orow[c * 32 + lane] = v;
    }
}

// ---------------- misc kernels ----------------

__global__ void node_dots_kernel(const float* __restrict__ H,
                                 const float* __restrict__ a_src,
                                 const float* __restrict__ a_dst,
                                 float* __restrict__ es, float* __restrict__ ed,
                                 int N, int D) {
    int warp = (blockIdx.x * blockDim.x + threadIdx.x) >> 5;
    int lane = threadIdx.x & 31;
    if (warp >= N) return;
    const float* row = H + (size_t)warp * D;
    float s1 = 0.f, s2 = 0.f;
    for (int j = lane; j < D; j += 32) {
        float v = row[j];
        s1 += v * a_src[j];
        s2 += v * a_dst[j];
    }
    #pragma unroll
    for (int o = 16; o; o >>= 1) {
        s1 += __shfl_down_sync(0xffffffffu, s1, o);
        s2 += __shfl_down_sync(0xffffffffu, s2, o);
    }
    if (lane == 0) { es[warp] = s1; ed[warp] = s2; }
}

__global__ void gather_rows4_kernel(const float4* __restrict__ in, const int* __restrict__ perm,
                                    float4* __restrict__ out, int N, int Dv) {
    size_t i = (size_t)blockIdx.x * blockDim.x + threadIdx.x;
    if (i >= (size_t)N * Dv) return;
    int r = (int)(i / Dv);
    int c = (int)(i - (size_t)r * Dv);
    out[i] = in[(size_t)perm[r] * Dv + c];
}

__global__ void summary_kernel(const float* __restrict__ h2, float* __restrict__ out, int N) {
    int c = blockIdx.x;
    __shared__ float sm[256];
    float s = 0.f;
    for (int i = threadIdx.x; i < N; i += blockDim.x)
        s += h2[(size_t)i * OUTD + c];
    sm[threadIdx.x] = s;
    __syncthreads();
    for (int o = 128; o; o >>= 1) {
        if (threadIdx.x < o) sm[threadIdx.x] += sm[threadIdx.x + o];
        __syncthreads();
    }
    if (threadIdx.x == 0) {
        float m = sm[0] / (float)N;
        out[c] = 1.f / (1.f + expf(-m));
    }
}

// ---------------- host orchestration ----------------

template<int DCH, bool ROUND_OUT>
static void run_gat(const float* H,
                    const float* a_src, const float* a_dst,
                    const int* rs, const int* csrc,
                    float* es, float* ed,
                    float* out, int ldo) {
    node_dots_kernel<<<(NN * 32 + 255) / 256, 256>>>(H, a_src, a_dst, es, ed, NN, DCH * 128);
    gat_fused_kernel<DCH, ROUND_OUT><<<(NN * 8 * 32 + 255) / 256, 256>>>(H, es, ed, rs, csrc, out, ldo, NN);
}

extern "C" void kernel_launch(void* const* d_in, const int* in_sizes, int n_in,
                              void* d_out, int out_size) {
    const float* features    = (const float*)d_in[0];
    const float* im_features = (const float*)d_in[1];
    const float* W1x         = (const float*)d_in[2];
    const float* a1x_src     = (const float*)d_in[3];
    const float* a1x_dst     = (const float*)d_in[4];
    const float* W1r         = (const float*)d_in[5];
    const float* a1r_src     = (const float*)d_in[6];
    const float* a1r_dst     = (const float*)d_in[7];
    const float* W2          = (const float*)d_in[8];
    const float* a3_src      = (const float*)d_in[9];
    const float* a3_dst      = (const float*)d_in[10];
    const int*   edge_index  = (const int*)d_in[11];
    const int*   perm        = (const int*)d_in[12];

    const int* src = edge_index;
    const int* dst = edge_index + EE;

    cudaFuncSetAttribute(tf32_gemm<true >, cudaFuncAttributeMaxDynamicSharedMemorySize, smem_bytes());
    cudaFuncSetAttribute(tf32_gemm<false>, cudaFuncAttributeMaxDynamicSharedMemorySize, smem_bytes());

    void* p;
    cudaGetSymbolAddress(&p, g_H1x);  float* H1x  = (float*)p;
    cudaGetSymbolAddress(&p, g_H1r);  float* H1r  = (float*)p;
    cudaGetSymbolAddress(&p, g_Hgx);  float* Hgx  = (float*)p;
    cudaGetSymbolAddress(&p, g_Hgr);  float* Hgr  = (float*)p;
    cudaGetSymbolAddress(&p, g_t);    float* tbuf = (float*)p;
    cudaGetSymbolAddress(&p, g_hdec); float* hdec = (float*)p;
    cudaGetSymbolAddress(&p, g_h3);   float* h3   = (float*)p;
    cudaGetSymbolAddress(&p, g_es);   float* es   = (float*)p;
    cudaGetSymbolAddress(&p, g_ed);   float* ed   = (float*)p;
    cudaGetSymbolAddress(&p, g_deg);  int*   deg  = (int*)p;
    cudaGetSymbolAddress(&p, g_rs);   int*   rs   = (int*)p;
    cudaGetSymbolAddress(&p, g_cur);  int*   cur  = (int*)p;
    cudaGetSymbolAddress(&p, g_csrc); int*   csrc = (int*)p;
    cudaGetSymbolAddress(&p, g_W1xc); float* W1xc = (float*)p;
    cudaGetSymbolAddress(&p, g_W1rc); float* W1rc = (float*)p;
    cudaGetSymbolAddress(&p, g_W2c);  float* W2c  = (float*)p;
    cudaGetSymbolAddress(&p, g_W1xt); float* W1xt = (float*)p;
    cudaGetSymbolAddress(&p, g_W1rt); float* W1rt = (float*)p;
    cudaGetSymbolAddress(&p, g_W2t);  float* W2t  = (float*)p;

    float* out = (float*)d_out;
    const size_t S_h2  = (size_t)NN * OUTD;
    const size_t S_h4x = (size_t)NN * INX;
    const size_t S_h4r = (size_t)NN * INR;
    const size_t passSz = S_h2 + S_h4x + S_h4r;

    // ---- weight prep ----
    cvt_tf32_kernel<<<(INX * NH + 255) / 256, 256>>>(W1x, W1xc, INX * NH);
    cvt_tf32_kernel<<<(INR * NH + 255) / 256, 256>>>(W1r, W1rc, INR * NH);
    cvt_tf32_kernel<<<(D2 * OUTD + 255) / 256, 256>>>(W2,  W2c,  D2 * OUTD);
    {
        dim3 blk(32, 8);
        dim3 g1((NH + 31) / 32, (INX + 31) / 32);
        transpose_cvt_kernel<<<g1, blk>>>(W1x, W1xt, INX, NH);
        dim3 g2((NH + 31) / 32, (INR + 31) / 32);
        transpose_cvt_kernel<<<g2, blk>>>(W1r, W1rt, INR, NH);
        dim3 g3((OUTD + 31) / 32, (D2 + 31) / 32);
        transpose_cvt_kernel<<<g3, blk>>>(W2, W2t, D2, OUTD);
    }

    // ---- CSR build ----
    cudaMemsetAsync(deg, 0, NN * sizeof(int));
    deg_kernel<<<(EE + 255) / 256, 256>>>(dst, deg, EE);
    scan_kernel<<<1, 1024>>>(deg, rs, NN);
    cudaMemcpyAsync(cur, rs, NN * sizeof(int), cudaMemcpyDeviceToDevice);
    scatter_kernel<<<(EE + 255) / 256, 256>>>(src, dst, cur, csrc, EE);

    // Big input GEMMs once; permuted pass reuses rows via gather.
    sgemm<true >(features,    W1xt, H1x, NN, NH, INX, INX);
    sgemm<true >(im_features, W1rt, H1r, NN, NH, INR, INR);

    for (int pass = 0; pass < 2; pass++) {
        const float* Hx = H1x;
        const float* Hr = H1r;
        if (pass) {
            size_t n4 = (size_t)NN * (NH / 4);
            gather_rows4_kernel<<<(unsigned)((n4 + 255) / 256), 256>>>((const float4*)H1x, perm, (float4*)Hgx, NN, NH / 4);
            gather_rows4_kernel<<<(unsigned)((n4 + 255) / 256), 256>>>((const float4*)H1r, perm, (float4*)Hgr, NN, NH / 4);
            Hx = Hgx; Hr = Hgr;
        }

        // encode GATs: outputs (tbuf) feed only tf32-GEMM A -> pre-rounded
        run_gat<2, true >(Hx, a1x_src, a1x_dst, rs, csrc, es, ed, tbuf,      D2);
        run_gat<2, true >(Hr, a1r_src, a1r_dst, rs, csrc, es, ed, tbuf + NH, D2);

        float* h2  = out + (size_t)pass * passSz;
        float* h4x = h2 + S_h2;
        float* h4r = h4x + S_h4x;

        sgemm<false>(tbuf, W2t, h2,  NN, OUTD, D2,  D2);    // A=tbuf pre-rounded
        sgemm<true >(h2,   W2c, hdec, NN, D2,  OUTD, OUTD); // A=h2 (output buffer, raw fp32)

        // decode GAT: h3 feeds only the two projection GEMMs -> pre-rounded
        run_gat<4, true >(hdec, a3_src, a3_dst, rs, csrc, es, ed, h3, D2);

        sgemm<false>(h3,      W1xc, h4x, NN, INX, NH, D2);
        sgemm<false>(h3 + NH, W1rc, h4r, NN, INR, NH, D2);
    }

    summary_kernel<<<OUTD, 256>>>(out, out + 2 * passSz, NN);
}